// round 13
// baseline (speedup 1.0000x reference)
#include <cuda_runtime.h>
#include <cuda_bf16.h>
#include <math.h>
#include <stdint.h>

#define B_   8
#define S_   4096
#define D_   256
#define SEG_ 128
#define E_   32
#define MASKVAL (-3.402823466e38f)

#define SEQ_ST 264   // halves
#define WB_ST  72    // halves

// smem byte offsets
#define OFF_SEQ_H 0
#define OFF_SEQ_L 67584
#define OFF_WBUF  135168     // 2 bufs x 36864
#define OFF_BIAS  208896
#define OFF_POOL  209920
#define SMEM_TOT  218112

__device__ __nv_bfloat16 g_w[8 * 18432];
__device__ int g_fix[E_];

// ---------------------------------------------------------------------------
__global__ void prep_fix_kernel(const float* __restrict__ w,
                                const float* __restrict__ mask) {
    int e = blockIdx.x, t = threadIdx.x;
    #pragma unroll
    for (int i = 0; i < 8; i++) {
        int idx = (e * 256 + t) + i * 8192;
        int m = idx >> 8, d = idx & 255;
        float v = w[idx];
        __nv_bfloat16 h = __float2bfloat16(v);
        __nv_bfloat16 l = __float2bfloat16(v - __bfloat162float(h));
        int hh = m >> 7, mloc = m & 127, c = d >> 6, kk = d & 63;
        int j = hh * 4 + c;
        int off = j * 18432 + mloc * 72 + kk;
        g_w[off] = h;
        g_w[off + 9216] = l;
    }
    if (t == 0) g_fix[e] = 0;
    __syncthreads();

    int warp = t >> 5, lane = t & 31;
    int found = 0;
    for (int r = warp; r < B_ * SEG_; r += 8) {
        int b = r >> 7, l = r & 127;
        const float* row = mask + ((size_t)b * S_ + (size_t)e * SEG_ + l) * S_
                                + (size_t)e * SEG_;
        int allm = 1;
        #pragma unroll
        for (int k = 0; k < 4; k++)
            if (row[lane + 32 * k] != MASKVAL) allm = 0;
        if (__all_sync(0xffffffffu, allm)) { found = 1; break; }
    }
    if (found && lane == 0) atomicOr(&g_fix[e], 1);
}

// ---------------------------------------------------------------------------
__device__ __forceinline__ void ldsm4(unsigned a, unsigned& r0, unsigned& r1,
                                      unsigned& r2, unsigned& r3) {
    asm volatile("ldmatrix.sync.aligned.m8n8.x4.shared.b16 {%0,%1,%2,%3},[%4];"
                 : "=r"(r0), "=r"(r1), "=r"(r2), "=r"(r3) : "r"(a));
}
__device__ __forceinline__ void ldsm4t(unsigned a, unsigned& r0, unsigned& r1,
                                       unsigned& r2, unsigned& r3) {
    asm volatile("ldmatrix.sync.aligned.m8n8.x4.trans.shared.b16 {%0,%1,%2,%3},[%4];"
                 : "=r"(r0), "=r"(r1), "=r"(r2), "=r"(r3) : "r"(a));
}
// NOTE: non-volatile — lets ptxas interleave independent MMA chains.
__device__ __forceinline__ void mma16816(float* c, unsigned a0, unsigned a1,
                                         unsigned a2, unsigned a3,
                                         unsigned b0, unsigned b1) {
    asm("mma.sync.aligned.m16n8k16.row.col.f32.bf16.bf16.f32 "
        "{%0,%1,%2,%3},{%4,%5,%6,%7},{%8,%9},{%0,%1,%2,%3};"
        : "+f"(c[0]), "+f"(c[1]), "+f"(c[2]), "+f"(c[3])
        : "r"(a0), "r"(a1), "r"(a2), "r"(a3), "r"(b0), "r"(b1));
}
__device__ __forceinline__ unsigned packhi(float a, float b) {
    __nv_bfloat162 p;
    p.x = __float2bfloat16(a); p.y = __float2bfloat16(b);
    return *(unsigned*)&p;
}
__device__ __forceinline__ unsigned packlo(float a, float b, unsigned hi) {
    __nv_bfloat162 h = *(__nv_bfloat162*)&hi;
    __nv_bfloat162 p;
    p.x = __float2bfloat16(a - __bfloat162float(h.x));
    p.y = __float2bfloat16(b - __bfloat162float(h.y));
    return *(unsigned*)&p;
}
__device__ __forceinline__ void cpasync16(unsigned dst, const void* src) {
    asm volatile("cp.async.cg.shared.global [%0],[%1],16;"
                 :: "r"(dst), "l"(src));
}
#define CP_COMMIT() asm volatile("cp.async.commit_group;" ::: "memory")
#define CP_WAIT0()  asm volatile("cp.async.wait_group 0;" ::: "memory")

// ---------------------------------------------------------------------------
__global__ void __launch_bounds__(256, 1)
main_kernel(const float* __restrict__ hidden,
            const float* __restrict__ maskp,
            const float* __restrict__ bvec,
            float* __restrict__ out)
{
    extern __shared__ char smc[];
    const unsigned sb = (unsigned)__cvta_generic_to_shared(smc);

    float* bias = (float*)(smc + OFF_BIAS);
    float* pool = (float*)(smc + OFF_POOL);

    const int t = threadIdx.x;
    const int lane = t & 31, wi = t >> 5;
    const int rg = lane >> 2, tg = lane & 3;
    const int e = blockIdx.x, bb = blockIdx.y;

    auto load_chunk = [&](int j, int bufi) {
        unsigned dst = sb + OFF_WBUF + (unsigned)bufi * 36864 + (unsigned)t * 16;
        const char* src = (const char*)g_w + (size_t)j * 36864 + (size_t)t * 16;
        #pragma unroll
        for (int i = 0; i < 9; i++)
            cpasync16(dst + i * 4096, src + i * 4096);
        CP_COMMIT();
    };
    load_chunk(0, 0);

    // ---- load seq tile, split bf16 hi/lo ----
    const float* seq_g = hidden + ((size_t)bb * S_ + (size_t)e * SEG_) * D_;
    for (int i = t; i < SEG_ * D_ / 4; i += 256) {
        int l = i >> 6, d = (i & 63) << 2;
        float4 v = *(const float4*)(seq_g + l * D_ + d);
        __nv_bfloat162 h0, h1, l0, l1;
        h0.x = __float2bfloat16(v.x); h0.y = __float2bfloat16(v.y);
        h1.x = __float2bfloat16(v.z); h1.y = __float2bfloat16(v.w);
        l0.x = __float2bfloat16(v.x - __bfloat162float(h0.x));
        l0.y = __float2bfloat16(v.y - __bfloat162float(h0.y));
        l1.x = __float2bfloat16(v.z - __bfloat162float(h1.x));
        l1.y = __float2bfloat16(v.w - __bfloat162float(h1.y));
        __nv_bfloat16* sh = (__nv_bfloat16*)(smc + OFF_SEQ_H) + l * SEQ_ST + d;
        __nv_bfloat16* sl = (__nv_bfloat16*)(smc + OFF_SEQ_L) + l * SEQ_ST + d;
        *(__nv_bfloat162*)sh = h0; *(__nv_bfloat162*)(sh + 2) = h1;
        *(__nv_bfloat162*)sl = l0; *(__nv_bfloat162*)(sl + 2) = l1;
    }
    bias[t] = bvec[t];
    const int fixe = g_fix[e];

    auto adrA = [&](unsigned off, int st, int r0, int k0) -> unsigned {
        int r = r0 + (lane & 7) + ((lane >> 3) & 1) * 8;
        int c = k0 + ((lane >> 4) & 1) * 8;
        return sb + off + (unsigned)((r * st + c) * 2);
    };
    auto adrB = [&](unsigned off, int st, int n0, int k0) -> unsigned {
        int r = n0 + (lane & 7) + ((lane >> 4) & 1) * 8;
        int c = k0 + ((lane >> 3) & 1) * 8;
        return sb + off + (unsigned)((r * st + c) * 2);
    };
    auto adrBt = [&](unsigned off, int st, int k0, int d0) -> unsigned {
        int r = k0 + (lane & 7) + ((lane >> 3) & 1) * 8;
        int c = d0 + ((lane >> 4) & 1) * 8;
        return sb + off + (unsigned)((r * st + c) * 2);
    };

    // =========== Phase A: trsf = tanh(seq @ w^T + b), streamed ============
    unsigned pAh[64], pAl[64];
    float accA[16][4];

    for (int j = 0; j < 8; j++) {           // chunk: h = j>>2, k64 = j&3
        CP_WAIT0();
        __syncthreads();
        if (j < 7) load_chunk(j + 1, (j + 1) & 1);

        if ((j & 3) == 0) {
            int h = j >> 2;
            #pragma unroll
            for (int jj = 0; jj < 16; jj++) {
                int m0 = h * 128 + jj * 8 + tg * 2;
                float b0 = bias[m0], b1 = bias[m0 + 1];
                accA[jj][0] = b0; accA[jj][1] = b1;
                accA[jj][2] = b0; accA[jj][3] = b1;
            }
        }

        unsigned bufB = OFF_WBUF + (unsigned)(j & 1) * 36864;
        #pragma unroll
        for (int kl = 0; kl < 4; kl++) {
            int kq = (j & 3) * 4 + kl;
            unsigned ah0, ah1, ah2, ah3, am0, am1, am2, am3;
            ldsm4(adrA(OFF_SEQ_H, SEQ_ST, wi * 16, kq * 16), ah0, ah1, ah2, ah3);
            ldsm4(adrA(OFF_SEQ_L, SEQ_ST, wi * 16, kq * 16), am0, am1, am2, am3);
            #pragma unroll
            for (int p = 0; p < 8; p += 2) {
                unsigned bh0, bh1, bh2, bh3, bl0, bl1, bl2, bl3;
                unsigned ch0, ch1, ch2, ch3, cl0, cl1, cl2, cl3;
                ldsm4(adrB(bufB, WB_ST, p * 16, kl * 16), bh0, bh1, bh2, bh3);
                ldsm4(adrB(bufB + 18432, WB_ST, p * 16, kl * 16), bl0, bl1, bl2, bl3);
                ldsm4(adrB(bufB, WB_ST, (p + 1) * 16, kl * 16), ch0, ch1, ch2, ch3);
                ldsm4(adrB(bufB + 18432, WB_ST, (p + 1) * 16, kl * 16), cl0, cl1, cl2, cl3);
                // 4 independent accumulators, round-robin (dep distance 4)
                mma16816(accA[2*p],   ah0, ah1, ah2, ah3, bh0, bh1);
                mma16816(accA[2*p+1], ah0, ah1, ah2, ah3, bh2, bh3);
                mma16816(accA[2*p+2], ah0, ah1, ah2, ah3, ch0, ch1);
                mma16816(accA[2*p+3], ah0, ah1, ah2, ah3, ch2, ch3);
                mma16816(accA[2*p],   ah0, ah1, ah2, ah3, bl0, bl1);
                mma16816(accA[2*p+1], ah0, ah1, ah2, ah3, bl2, bl3);
                mma16816(accA[2*p+2], ah0, ah1, ah2, ah3, cl0, cl1);
                mma16816(accA[2*p+3], ah0, ah1, ah2, ah3, cl2, cl3);
                mma16816(accA[2*p],   am0, am1, am2, am3, bh0, bh1);
                mma16816(accA[2*p+1], am0, am1, am2, am3, bh2, bh3);
                mma16816(accA[2*p+2], am0, am1, am2, am3, ch0, ch1);
                mma16816(accA[2*p+3], am0, am1, am2, am3, ch2, ch3);
            }
        }

        if ((j & 3) == 3) {
            int h = j >> 2;
            #pragma unroll
            for (int jj = 0; jj < 16; jj++) {
                float v0 = tanhf(accA[jj][0]), v1 = tanhf(accA[jj][1]);
                float v2 = tanhf(accA[jj][2]), v3 = tanhf(accA[jj][3]);
                int base = h * 32 + (jj >> 1) * 4 + (jj & 1) * 2;
                pAh[base]     = packhi(v0, v1);
                pAl[base]     = packlo(v0, v1, pAh[base]);
                pAh[base + 1] = packhi(v2, v3);
                pAl[base + 1] = packlo(v2, v3, pAh[base + 1]);
            }
        }
    }

    // =========== Phase B: scores = trsf @ seq^T (acc init = mask) =========
    float accB[16][4];
    {
        int l0 = wi * 16 + rg;
        const float* mr0 = maskp + ((size_t)(bb * S_ + e * SEG_ + l0)) * S_
                                 + (size_t)e * SEG_;
        const float* mr1 = mr0 + (size_t)8 * S_;
        #pragma unroll
        for (int j = 0; j < 16; j++) {
            float2 m0 = *(const float2*)(mr0 + 8 * j + tg * 2);
            float2 m1 = *(const float2*)(mr1 + 8 * j + tg * 2);
            if (fixe && l0 == 0) { m0.x = 0.0f; m0.y = 0.0f; }
            accB[j][0] = m0.x; accB[j][1] = m0.y;
            accB[j][2] = m1.x; accB[j][3] = m1.y;
        }
    }

    #pragma unroll
    for (int kc = 0; kc < 16; kc++) {
        unsigned Ah0 = pAh[kc*4], Ah1 = pAh[kc*4+1], Ah2 = pAh[kc*4+2], Ah3 = pAh[kc*4+3];
        unsigned Al0 = pAl[kc*4], Al1 = pAl[kc*4+1], Al2 = pAl[kc*4+2], Al3 = pAl[kc*4+3];
        #pragma unroll
        for (int p = 0; p < 8; p += 2) {
            unsigned bh0, bh1, bh2, bh3, bl0, bl1, bl2, bl3;
            unsigned ch0, ch1, ch2, ch3, cl0, cl1, cl2, cl3;
            ldsm4(adrB(OFF_SEQ_H, SEQ_ST, p * 16, kc * 16), bh0, bh1, bh2, bh3);
            ldsm4(adrB(OFF_SEQ_L, SEQ_ST, p * 16, kc * 16), bl0, bl1, bl2, bl3);
            ldsm4(adrB(OFF_SEQ_H, SEQ_ST, (p + 1) * 16, kc * 16), ch0, ch1, ch2, ch3);
            ldsm4(adrB(OFF_SEQ_L, SEQ_ST, (p + 1) * 16, kc * 16), cl0, cl1, cl2, cl3);
            mma16816(accB[2*p],   Ah0, Ah1, Ah2, Ah3, bh0, bh1);
            mma16816(accB[2*p+1], Ah0, Ah1, Ah2, Ah3, bh2, bh3);
            mma16816(accB[2*p+2], Ah0, Ah1, Ah2, Ah3, ch0, ch1);
            mma16816(accB[2*p+3], Ah0, Ah1, Ah2, Ah3, ch2, ch3);
            mma16816(accB[2*p],   Ah0, Ah1, Ah2, Ah3, bl0, bl1);
            mma16816(accB[2*p+1], Ah0, Ah1, Ah2, Ah3, bl2, bl3);
            mma16816(accB[2*p+2], Ah0, Ah1, Ah2, Ah3, cl0, cl1);
            mma16816(accB[2*p+3], Ah0, Ah1, Ah2, Ah3, cl2, cl3);
            mma16816(accB[2*p],   Al0, Al1, Al2, Al3, bh0, bh1);
            mma16816(accB[2*p+1], Al0, Al1, Al2, Al3, bh2, bh3);
            mma16816(accB[2*p+2], Al0, Al1, Al2, Al3, ch0, ch1);
            mma16816(accB[2*p+3], Al0, Al1, Al2, Al3, ch2, ch3);
        }
    }

    // ===== in-register softmax (rows rg and rg+8) =====
    {
        float mx0 = -3.4e38f, mx1 = -3.4e38f;
        #pragma unroll
        for (int j = 0; j < 16; j++) {
            mx0 = fmaxf(mx0, fmaxf(accB[j][0], accB[j][1]));
            mx1 = fmaxf(mx1, fmaxf(accB[j][2], accB[j][3]));
        }
        mx0 = fmaxf(mx0, __shfl_xor_sync(0xffffffffu, mx0, 1));
        mx0 = fmaxf(mx0, __shfl_xor_sync(0xffffffffu, mx0, 2));
        mx1 = fmaxf(mx1, __shfl_xor_sync(0xffffffffu, mx1, 1));
        mx1 = fmaxf(mx1, __shfl_xor_sync(0xffffffffu, mx1, 2));
        float s0 = 0.0f, s1 = 0.0f;
        #pragma unroll
        for (int j = 0; j < 16; j++) {
            accB[j][0] = __expf(accB[j][0] - mx0);
            accB[j][1] = __expf(accB[j][1] - mx0);
            accB[j][2] = __expf(accB[j][2] - mx1);
            accB[j][3] = __expf(accB[j][3] - mx1);
            s0 += accB[j][0] + accB[j][1];
            s1 += accB[j][2] + accB[j][3];
        }
        s0 += __shfl_xor_sync(0xffffffffu, s0, 1);
        s0 += __shfl_xor_sync(0xffffffffu, s0, 2);
        s1 += __shfl_xor_sync(0xffffffffu, s1, 1);
        s1 += __shfl_xor_sync(0xffffffffu, s1, 2);
        float i0 = 1.0f / s0, i1 = 1.0f / s1;
        #pragma unroll
        for (int j = 0; j < 16; j++) {
            accB[j][0] *= i0; accB[j][1] *= i0;
            accB[j][2] *= i1; accB[j][3] *= i1;
        }
    }

    // pack attn to phase-C A-frags
    unsigned aCh[32], aCl[32];
    #pragma unroll
    for (int j = 0; j < 16; j++) {
        int base = (j >> 1) * 4 + (j & 1) * 2;
        aCh[base]     = packhi(accB[j][0], accB[j][1]);
        aCl[base]     = packlo(accB[j][0], accB[j][1], aCh[base]);
        aCh[base + 1] = packhi(accB[j][2], accB[j][3]);
        aCl[base + 1] = packlo(accB[j][2], accB[j][3], aCh[base + 1]);
    }

    // =========== Phase C: ctx = attn @ seq, pooled ========================
    #pragma unroll
    for (int half = 0; half < 2; half++) {
        float accC[16][4];
        #pragma unroll
        for (int j = 0; j < 16; j++)
            #pragma unroll
            for (int q = 0; q < 4; q++) accC[j][q] = 0.0f;

        #pragma unroll
        for (int kc = 0; kc < 8; kc++) {
            unsigned Ah0 = aCh[kc*4], Ah1 = aCh[kc*4+1], Ah2 = aCh[kc*4+2], Ah3 = aCh[kc*4+3];
            unsigned Al0 = aCl[kc*4], Al1 = aCl[kc*4+1], Al2 = aCl[kc*4+2], Al3 = aCl[kc*4+3];
            #pragma unroll
            for (int p = 0; p < 8; p += 2) {
                int d0 = half * 128 + p * 16;
                unsigned bh0, bh1, bh2, bh3, bl0, bl1, bl2, bl3;
                unsigned ch0, ch1, ch2, ch3, cl0, cl1, cl2, cl3;
                ldsm4t(adrBt(OFF_SEQ_H, SEQ_ST, kc * 16, d0), bh0, bh1, bh2, bh3);
                ldsm4t(adrBt(OFF_SEQ_L, SEQ_ST, kc * 16, d0), bl0, bl1, bl2, bl3);
                ldsm4t(adrBt(OFF_SEQ_H, SEQ_ST, kc * 16, d0 + 16), ch0, ch1, ch2, ch3);
                ldsm4t(adrBt(OFF_SEQ_L, SEQ_ST, kc * 16, d0 + 16), cl0, cl1, cl2, cl3);
                mma16816(accC[2*p],   Ah0, Ah1, Ah2, Ah3, bh0, bh1);
                mma16816(accC[2*p+1], Ah0, Ah1, Ah2, Ah3, bh2, bh3);
                mma16816(accC[2*p+2], Ah0, Ah1, Ah2, Ah3, ch0, ch1);
                mma16816(accC[2*p+3], Ah0, Ah1, Ah2, Ah3, ch2, ch3);
                mma16816(accC[2*p],   Ah0, Ah1, Ah2, Ah3, bl0, bl1);
                mma16816(accC[2*p+1], Ah0, Ah1, Ah2, Ah3, bl2, bl3);
                mma16816(accC[2*p+2], Ah0, Ah1, Ah2, Ah3, cl0, cl1);
                mma16816(accC[2*p+3], Ah0, Ah1, Ah2, Ah3, cl2, cl3);
                mma16816(accC[2*p],   Al0, Al1, Al2, Al3, bh0, bh1);
                mma16816(accC[2*p+1], Al0, Al1, Al2, Al3, bh2, bh3);
                mma16816(accC[2*p+2], Al0, Al1, Al2, Al3, ch0, ch1);
                mma16816(accC[2*p+3], Al0, Al1, Al2, Al3, ch2, ch3);
            }
        }
        #pragma unroll
        for (int j = 0; j < 16; j++) {
            float m0 = fmaxf(accC[j][0], accC[j][2]);
            float m1 = fmaxf(accC[j][1], accC[j][3]);
            m0 = fmaxf(m0, __shfl_xor_sync(0xffffffffu, m0, 4));
            m0 = fmaxf(m0, __shfl_xor_sync(0xffffffffu, m0, 8));
            m0 = fmaxf(m0, __shfl_xor_sync(0xffffffffu, m0, 16));
            m1 = fmaxf(m1, __shfl_xor_sync(0xffffffffu, m1, 4));
            m1 = fmaxf(m1, __shfl_xor_sync(0xffffffffu, m1, 8));
            m1 = fmaxf(m1, __shfl_xor_sync(0xffffffffu, m1, 16));
            if (rg == 0) {
                int d = half * 128 + 8 * j + tg * 2;
                pool[wi * 256 + d]     = m0;
                pool[wi * 256 + d + 1] = m1;
            }
        }
    }
    __syncthreads();

    // ---- final pool reduce over 8 warps ----
    {
        float mx = -3.4e38f;
        #pragma unroll
        for (int w = 0; w < 8; w++) mx = fmaxf(mx, pool[w * 256 + t]);
        out[((size_t)bb * E_ + e) * D_ + t] = mx;
    }

    // new_mask[b][e][s] = (s/128 == e)
    float* nm = out + (size_t)B_ * E_ * D_ + ((size_t)bb * E_ + e) * S_;
    for (int s = t; s < S_; s += 256)
        nm[s] = ((s >> 7) == e) ? 1.0f : 0.0f;
}

// ---------------------------------------------------------------------------
extern "C" void kernel_launch(void* const* d_in, const int* in_sizes, int n_in,
                              void* d_out, int out_size) {
    const float* hidden = (const float*)d_in[0];
    const float* mask   = (const float*)d_in[1];
    const float* w      = (const float*)d_in[2];
    const float* bvec   = (const float*)d_in[3];
    float* out = (float*)d_out;
    (void)in_sizes; (void)n_in; (void)out_size;

    prep_fix_kernel<<<E_, 256>>>(w, mask);

    cudaFuncSetAttribute(main_kernel,
                         cudaFuncAttributeMaxDynamicSharedMemorySize, SMEM_TOT);
    main_kernel<<<dim3(E_, B_), 256, SMEM_TOT>>>(hidden, mask, bvec, out);
}

// round 15
// speedup vs baseline: 1.0108x; 1.0108x over previous
#include <cuda_runtime.h>
#include <cuda_bf16.h>
#include <math.h>
#include <stdint.h>

#define B_   8
#define S_   4096
#define D_   256
#define SEG_ 128
#define E_   32
#define MASKVAL (-3.402823466e38f)

#define SEQ_ST 264   // halves
#define WB_ST  72    // halves

// smem byte offsets
#define OFF_SEQ_H 0
#define OFF_SEQ_L 67584
#define OFF_WBUF  135168     // 2 bufs x 36864
#define OFF_BIAS  208896
#define OFF_POOL  209920
#define SMEM_TOT  218112

__device__ __nv_bfloat16 g_w[8 * 18432];
__device__ int g_fix[E_];

// ---------------------------------------------------------------------------
__global__ void prep_fix_kernel(const float* __restrict__ w,
                                const float* __restrict__ mask) {
    int e = blockIdx.x, t = threadIdx.x;
    #pragma unroll
    for (int i = 0; i < 8; i++) {
        int idx = (e * 256 + t) + i * 8192;
        int m = idx >> 8, d = idx & 255;
        float v = w[idx];
        __nv_bfloat16 h = __float2bfloat16(v);
        __nv_bfloat16 l = __float2bfloat16(v - __bfloat162float(h));
        int hh = m >> 7, mloc = m & 127, c = d >> 6, kk = d & 63;
        int j = hh * 4 + c;
        int off = j * 18432 + mloc * 72 + kk;
        g_w[off] = h;
        g_w[off + 9216] = l;
    }
    if (t == 0) g_fix[e] = 0;
    __syncthreads();

    int warp = t >> 5, lane = t & 31;
    int found = 0;
    for (int r = warp; r < B_ * SEG_; r += 8) {
        int b = r >> 7, l = r & 127;
        const float* row = mask + ((size_t)b * S_ + (size_t)e * SEG_ + l) * S_
                                + (size_t)e * SEG_;
        int allm = 1;
        #pragma unroll
        for (int k = 0; k < 4; k++)
            if (row[lane + 32 * k] != MASKVAL) allm = 0;
        if (__all_sync(0xffffffffu, allm)) { found = 1; break; }
    }
    if (found && lane == 0) atomicOr(&g_fix[e], 1);
}

// ---------------------------------------------------------------------------
__device__ __forceinline__ void ldsm4(unsigned a, unsigned& r0, unsigned& r1,
                                      unsigned& r2, unsigned& r3) {
    asm volatile("ldmatrix.sync.aligned.m8n8.x4.shared.b16 {%0,%1,%2,%3},[%4];"
                 : "=r"(r0), "=r"(r1), "=r"(r2), "=r"(r3) : "r"(a));
}
__device__ __forceinline__ void ldsm4t(unsigned a, unsigned& r0, unsigned& r1,
                                       unsigned& r2, unsigned& r3) {
    asm volatile("ldmatrix.sync.aligned.m8n8.x4.trans.shared.b16 {%0,%1,%2,%3},[%4];"
                 : "=r"(r0), "=r"(r1), "=r"(r2), "=r"(r3) : "r"(a));
}
__device__ __forceinline__ void mma16816(float* c, unsigned a0, unsigned a1,
                                         unsigned a2, unsigned a3,
                                         unsigned b0, unsigned b1) {
    asm("mma.sync.aligned.m16n8k16.row.col.f32.bf16.bf16.f32 "
        "{%0,%1,%2,%3},{%4,%5,%6,%7},{%8,%9},{%0,%1,%2,%3};"
        : "+f"(c[0]), "+f"(c[1]), "+f"(c[2]), "+f"(c[3])
        : "r"(a0), "r"(a1), "r"(a2), "r"(a3), "r"(b0), "r"(b1));
}
__device__ __forceinline__ unsigned packhi(float a, float b) {
    __nv_bfloat162 p;
    p.x = __float2bfloat16(a); p.y = __float2bfloat16(b);
    return *(unsigned*)&p;
}
__device__ __forceinline__ unsigned packlo(float a, float b, unsigned hi) {
    __nv_bfloat162 h = *(__nv_bfloat162*)&hi;
    __nv_bfloat162 p;
    p.x = __float2bfloat16(a - __bfloat162float(h.x));
    p.y = __float2bfloat16(b - __bfloat162float(h.y));
    return *(unsigned*)&p;
}
__device__ __forceinline__ void cpasync16(unsigned dst, const void* src) {
    asm volatile("cp.async.cg.shared.global [%0],[%1],16;"
                 :: "r"(dst), "l"(src));
}
#define CP_COMMIT() asm volatile("cp.async.commit_group;" ::: "memory")
#define CP_WAIT0()  asm volatile("cp.async.wait_group 0;" ::: "memory")

// ---------------------------------------------------------------------------
__global__ void __launch_bounds__(256, 1)
main_kernel(const float* __restrict__ hidden,
            const float* __restrict__ maskp,
            const float* __restrict__ bvec,
            float* __restrict__ out)
{
    extern __shared__ char smc[];
    const unsigned sb = (unsigned)__cvta_generic_to_shared(smc);

    float* bias = (float*)(smc + OFF_BIAS);
    float* pool = (float*)(smc + OFF_POOL);

    const int t = threadIdx.x;
    const int lane = t & 31, wi = t >> 5;
    const int rg = lane >> 2, tg = lane & 3;
    const int e = blockIdx.x, bb = blockIdx.y;

    auto load_chunk = [&](int j, int bufi) {
        unsigned dst = sb + OFF_WBUF + (unsigned)bufi * 36864 + (unsigned)t * 16;
        const char* src = (const char*)g_w + (size_t)j * 36864 + (size_t)t * 16;
        #pragma unroll
        for (int i = 0; i < 9; i++)
            cpasync16(dst + i * 4096, src + i * 4096);
        CP_COMMIT();
    };
    load_chunk(0, 0);

    // ---- load seq tile, split bf16 hi/lo ----
    const float* seq_g = hidden + ((size_t)bb * S_ + (size_t)e * SEG_) * D_;
    for (int i = t; i < SEG_ * D_ / 4; i += 256) {
        int l = i >> 6, d = (i & 63) << 2;
        float4 v = *(const float4*)(seq_g + l * D_ + d);
        __nv_bfloat162 h0, h1, l0, l1;
        h0.x = __float2bfloat16(v.x); h0.y = __float2bfloat16(v.y);
        h1.x = __float2bfloat16(v.z); h1.y = __float2bfloat16(v.w);
        l0.x = __float2bfloat16(v.x - __bfloat162float(h0.x));
        l0.y = __float2bfloat16(v.y - __bfloat162float(h0.y));
        l1.x = __float2bfloat16(v.z - __bfloat162float(h1.x));
        l1.y = __float2bfloat16(v.w - __bfloat162float(h1.y));
        __nv_bfloat16* sh = (__nv_bfloat16*)(smc + OFF_SEQ_H) + l * SEQ_ST + d;
        __nv_bfloat16* sl = (__nv_bfloat16*)(smc + OFF_SEQ_L) + l * SEQ_ST + d;
        *(__nv_bfloat162*)sh = h0; *(__nv_bfloat162*)(sh + 2) = h1;
        *(__nv_bfloat162*)sl = l0; *(__nv_bfloat162*)(sl + 2) = l1;
    }
    bias[t] = bvec[t];
    const int fixe = g_fix[e];

    auto adrA = [&](unsigned off, int st, int r0, int k0) -> unsigned {
        int r = r0 + (lane & 7) + ((lane >> 3) & 1) * 8;
        int c = k0 + ((lane >> 4) & 1) * 8;
        return sb + off + (unsigned)((r * st + c) * 2);
    };
    auto adrB = [&](unsigned off, int st, int n0, int k0) -> unsigned {
        int r = n0 + (lane & 7) + ((lane >> 4) & 1) * 8;
        int c = k0 + ((lane >> 3) & 1) * 8;
        return sb + off + (unsigned)((r * st + c) * 2);
    };
    auto adrBt = [&](unsigned off, int st, int k0, int d0) -> unsigned {
        int r = k0 + (lane & 7) + ((lane >> 3) & 1) * 8;
        int c = d0 + ((lane >> 4) & 1) * 8;
        return sb + off + (unsigned)((r * st + c) * 2);
    };

    // =========== Phase A: trsf = tanh(seq @ w^T + b), streamed ============
    unsigned pAh[64], pAl[64];
    float accA[16][4];

    for (int j = 0; j < 8; j++) {           // chunk: h = j>>2, k64 = j&3
        CP_WAIT0();
        __syncthreads();
        if (j < 7) load_chunk(j + 1, (j + 1) & 1);

        if ((j & 3) == 0) {
            int h = j >> 2;
            #pragma unroll
            for (int jj = 0; jj < 16; jj++) {
                int m0 = h * 128 + jj * 8 + tg * 2;
                float b0 = bias[m0], b1 = bias[m0 + 1];
                accA[jj][0] = b0; accA[jj][1] = b1;
                accA[jj][2] = b0; accA[jj][3] = b1;
            }
        }

        unsigned bufB = OFF_WBUF + (unsigned)(j & 1) * 36864;
        unsigned ah0, ah1, ah2, ah3, am0, am1, am2, am3;
        unsigned cw[8], nw[8];
        // preload iteration 0's B frags
        ldsm4(adrB(bufB, WB_ST, 0, 0), cw[0], cw[1], cw[2], cw[3]);
        ldsm4(adrB(bufB + 18432, WB_ST, 0, 0), cw[4], cw[5], cw[6], cw[7]);

        #pragma unroll
        for (int it = 0; it < 32; it++) {
            int kl = it >> 3, p = it & 7;
            int kq = (j & 3) * 4 + kl;
            if (p == 0) {
                ldsm4(adrA(OFF_SEQ_H, SEQ_ST, wi * 16, kq * 16), ah0, ah1, ah2, ah3);
                ldsm4(adrA(OFF_SEQ_L, SEQ_ST, wi * 16, kq * 16), am0, am1, am2, am3);
            }
            if (it < 31) {
                int nkl = (it + 1) >> 3, np = (it + 1) & 7;
                ldsm4(adrB(bufB, WB_ST, np * 16, nkl * 16),
                      nw[0], nw[1], nw[2], nw[3]);
                ldsm4(adrB(bufB + 18432, WB_ST, np * 16, nkl * 16),
                      nw[4], nw[5], nw[6], nw[7]);
            }
            mma16816(accA[2*p],   ah0, ah1, ah2, ah3, cw[0], cw[1]);
            mma16816(accA[2*p+1], ah0, ah1, ah2, ah3, cw[2], cw[3]);
            mma16816(accA[2*p],   ah0, ah1, ah2, ah3, cw[4], cw[5]);
            mma16816(accA[2*p+1], ah0, ah1, ah2, ah3, cw[6], cw[7]);
            mma16816(accA[2*p],   am0, am1, am2, am3, cw[0], cw[1]);
            mma16816(accA[2*p+1], am0, am1, am2, am3, cw[2], cw[3]);
            #pragma unroll
            for (int q = 0; q < 8; q++) cw[q] = nw[q];
        }

        if ((j & 3) == 3) {
            int h = j >> 2;
            #pragma unroll
            for (int jj = 0; jj < 16; jj++) {
                float v0 = tanhf(accA[jj][0]), v1 = tanhf(accA[jj][1]);
                float v2 = tanhf(accA[jj][2]), v3 = tanhf(accA[jj][3]);
                int base = h * 32 + (jj >> 1) * 4 + (jj & 1) * 2;
                pAh[base]     = packhi(v0, v1);
                pAl[base]     = packlo(v0, v1, pAh[base]);
                pAh[base + 1] = packhi(v2, v3);
                pAl[base + 1] = packlo(v2, v3, pAh[base + 1]);
            }
        }
    }

    // =========== Phase B: scores = trsf @ seq^T (acc init = mask) =========
    float accB[16][4];
    {
        int l0 = wi * 16 + rg;
        const float* mr0 = maskp + ((size_t)(bb * S_ + e * SEG_ + l0)) * S_
                                 + (size_t)e * SEG_;
        const float* mr1 = mr0 + (size_t)8 * S_;
        #pragma unroll
        for (int j = 0; j < 16; j++) {
            float2 m0 = *(const float2*)(mr0 + 8 * j + tg * 2);
            float2 m1 = *(const float2*)(mr1 + 8 * j + tg * 2);
            if (fixe && l0 == 0) { m0.x = 0.0f; m0.y = 0.0f; }
            accB[j][0] = m0.x; accB[j][1] = m0.y;
            accB[j][2] = m1.x; accB[j][3] = m1.y;
        }
    }

    {
        unsigned cw[8], nw[8];
        ldsm4(adrB(OFF_SEQ_H, SEQ_ST, 0, 0), cw[0], cw[1], cw[2], cw[3]);
        ldsm4(adrB(OFF_SEQ_L, SEQ_ST, 0, 0), cw[4], cw[5], cw[6], cw[7]);
        #pragma unroll
        for (int it = 0; it < 128; it++) {
            int kc = it >> 3, p = it & 7;
            if (it < 127) {
                int nkc = (it + 1) >> 3, np = (it + 1) & 7;
                ldsm4(adrB(OFF_SEQ_H, SEQ_ST, np * 16, nkc * 16),
                      nw[0], nw[1], nw[2], nw[3]);
                ldsm4(adrB(OFF_SEQ_L, SEQ_ST, np * 16, nkc * 16),
                      nw[4], nw[5], nw[6], nw[7]);
            }
            unsigned Ah0 = pAh[kc*4], Ah1 = pAh[kc*4+1],
                     Ah2 = pAh[kc*4+2], Ah3 = pAh[kc*4+3];
            unsigned Al0 = pAl[kc*4], Al1 = pAl[kc*4+1],
                     Al2 = pAl[kc*4+2], Al3 = pAl[kc*4+3];
            mma16816(accB[2*p],   Ah0, Ah1, Ah2, Ah3, cw[0], cw[1]);
            mma16816(accB[2*p+1], Ah0, Ah1, Ah2, Ah3, cw[2], cw[3]);
            mma16816(accB[2*p],   Ah0, Ah1, Ah2, Ah3, cw[4], cw[5]);
            mma16816(accB[2*p+1], Ah0, Ah1, Ah2, Ah3, cw[6], cw[7]);
            mma16816(accB[2*p],   Al0, Al1, Al2, Al3, cw[0], cw[1]);
            mma16816(accB[2*p+1], Al0, Al1, Al2, Al3, cw[2], cw[3]);
            #pragma unroll
            for (int q = 0; q < 8; q++) cw[q] = nw[q];
        }
    }

    // ===== in-register softmax (rows rg and rg+8) =====
    {
        float mx0 = -3.4e38f, mx1 = -3.4e38f;
        #pragma unroll
        for (int j = 0; j < 16; j++) {
            mx0 = fmaxf(mx0, fmaxf(accB[j][0], accB[j][1]));
            mx1 = fmaxf(mx1, fmaxf(accB[j][2], accB[j][3]));
        }
        mx0 = fmaxf(mx0, __shfl_xor_sync(0xffffffffu, mx0, 1));
        mx0 = fmaxf(mx0, __shfl_xor_sync(0xffffffffu, mx0, 2));
        mx1 = fmaxf(mx1, __shfl_xor_sync(0xffffffffu, mx1, 1));
        mx1 = fmaxf(mx1, __shfl_xor_sync(0xffffffffu, mx1, 2));
        float s0 = 0.0f, s1 = 0.0f;
        #pragma unroll
        for (int j = 0; j < 16; j++) {
            accB[j][0] = __expf(accB[j][0] - mx0);
            accB[j][1] = __expf(accB[j][1] - mx0);
            accB[j][2] = __expf(accB[j][2] - mx1);
            accB[j][3] = __expf(accB[j][3] - mx1);
            s0 += accB[j][0] + accB[j][1];
            s1 += accB[j][2] + accB[j][3];
        }
        s0 += __shfl_xor_sync(0xffffffffu, s0, 1);
        s0 += __shfl_xor_sync(0xffffffffu, s0, 2);
        s1 += __shfl_xor_sync(0xffffffffu, s1, 1);
        s1 += __shfl_xor_sync(0xffffffffu, s1, 2);
        float i0 = 1.0f / s0, i1 = 1.0f / s1;
        #pragma unroll
        for (int j = 0; j < 16; j++) {
            accB[j][0] *= i0; accB[j][1] *= i0;
            accB[j][2] *= i1; accB[j][3] *= i1;
        }
    }

    // pack attn to phase-C A-frags
    unsigned aCh[32], aCl[32];
    #pragma unroll
    for (int j = 0; j < 16; j++) {
        int base = (j >> 1) * 4 + (j & 1) * 2;
        aCh[base]     = packhi(accB[j][0], accB[j][1]);
        aCl[base]     = packlo(accB[j][0], accB[j][1], aCh[base]);
        aCh[base + 1] = packhi(accB[j][2], accB[j][3]);
        aCl[base + 1] = packlo(accB[j][2], accB[j][3], aCh[base + 1]);
    }

    // =========== Phase C: ctx = attn @ seq, pooled ========================
    #pragma unroll
    for (int half = 0; half < 2; half++) {
        float accC[16][4];
        #pragma unroll
        for (int j = 0; j < 16; j++)
            #pragma unroll
            for (int q = 0; q < 4; q++) accC[j][q] = 0.0f;

        unsigned cw[8], nw[8];
        ldsm4t(adrBt(OFF_SEQ_H, SEQ_ST, 0, half * 128), cw[0], cw[1], cw[2], cw[3]);
        ldsm4t(adrBt(OFF_SEQ_L, SEQ_ST, 0, half * 128), cw[4], cw[5], cw[6], cw[7]);
        #pragma unroll
        for (int it = 0; it < 64; it++) {
            int kc = it >> 3, p = it & 7;
            if (it < 63) {
                int nkc = (it + 1) >> 3, np = (it + 1) & 7;
                ldsm4t(adrBt(OFF_SEQ_H, SEQ_ST, nkc * 16, half * 128 + np * 16),
                       nw[0], nw[1], nw[2], nw[3]);
                ldsm4t(adrBt(OFF_SEQ_L, SEQ_ST, nkc * 16, half * 128 + np * 16),
                       nw[4], nw[5], nw[6], nw[7]);
            }
            unsigned Ah0 = aCh[kc*4], Ah1 = aCh[kc*4+1],
                     Ah2 = aCh[kc*4+2], Ah3 = aCh[kc*4+3];
            unsigned Al0 = aCl[kc*4], Al1 = aCl[kc*4+1],
                     Al2 = aCl[kc*4+2], Al3 = aCl[kc*4+3];
            mma16816(accC[2*p],   Ah0, Ah1, Ah2, Ah3, cw[0], cw[1]);
            mma16816(accC[2*p+1], Ah0, Ah1, Ah2, Ah3, cw[2], cw[3]);
            mma16816(accC[2*p],   Ah0, Ah1, Ah2, Ah3, cw[4], cw[5]);
            mma16816(accC[2*p+1], Ah0, Ah1, Ah2, Ah3, cw[6], cw[7]);
            mma16816(accC[2*p],   Al0, Al1, Al2, Al3, cw[0], cw[1]);
            mma16816(accC[2*p+1], Al0, Al1, Al2, Al3, cw[2], cw[3]);
            #pragma unroll
            for (int q = 0; q < 8; q++) cw[q] = nw[q];
        }

        #pragma unroll
        for (int j = 0; j < 16; j++) {
            float m0 = fmaxf(accC[j][0], accC[j][2]);
            float m1 = fmaxf(accC[j][1], accC[j][3]);
            m0 = fmaxf(m0, __shfl_xor_sync(0xffffffffu, m0, 4));
            m0 = fmaxf(m0, __shfl_xor_sync(0xffffffffu, m0, 8));
            m0 = fmaxf(m0, __shfl_xor_sync(0xffffffffu, m0, 16));
            m1 = fmaxf(m1, __shfl_xor_sync(0xffffffffu, m1, 4));
            m1 = fmaxf(m1, __shfl_xor_sync(0xffffffffu, m1, 8));
            m1 = fmaxf(m1, __shfl_xor_sync(0xffffffffu, m1, 16));
            if (rg == 0) {
                int d = half * 128 + 8 * j + tg * 2;
                pool[wi * 256 + d]     = m0;
                pool[wi * 256 + d + 1] = m1;
            }
        }
    }
    __syncthreads();

    // ---- final pool reduce over 8 warps ----
    {
        float mx = -3.4e38f;
        #pragma unroll
        for (int w = 0; w < 8; w++) mx = fmaxf(mx, pool[w * 256 + t]);
        out[((size_t)bb * E_ + e) * D_ + t] = mx;
    }

    // new_mask[b][e][s] = (s/128 == e)
    float* nm = out + (size_t)B_ * E_ * D_ + ((size_t)bb * E_ + e) * S_;
    for (int s = t; s < S_; s += 256)
        nm[s] = ((s >> 7) == e) ? 1.0f : 0.0f;
}

// ---------------------------------------------------------------------------
extern "C" void kernel_launch(void* const* d_in, const int* in_sizes, int n_in,
                              void* d_out, int out_size) {
    const float* hidden = (const float*)d_in[0];
    const float* mask   = (const float*)d_in[1];
    const float* w      = (const float*)d_in[2];
    const float* bvec   = (const float*)d_in[3];
    float* out = (float*)d_out;
    (void)in_sizes; (void)n_in; (void)out_size;

    prep_fix_kernel<<<E_, 256>>>(w, mask);

    cudaFuncSetAttribute(main_kernel,
                         cudaFuncAttributeMaxDynamicSharedMemorySize, SMEM_TOT);
    main_kernel<<<dim3(E_, B_), 256, SMEM_TOT>>>(hidden, mask, bvec, out);
}

// round 16
// speedup vs baseline: 1.2318x; 1.2186x over previous
#include <cuda_runtime.h>
#include <cuda_fp16.h>
#include <math.h>
#include <stdint.h>

#define B_   8
#define S_   4096
#define D_   256
#define SEG_ 128
#define E_   32
#define MASKVAL (-3.402823466e38f)

#define SEQ_ST 264   // halves
#define WB_ST  72    // halves

// smem byte offsets
#define OFF_SEQ_H 0
#define OFF_SEQ_L 67584
#define OFF_WBUF  135168     // 2 bufs x 36864
#define OFF_BIAS  208896
#define OFF_POOL  209920
#define SMEM_TOT  218112

__device__ __half g_w[8 * 18432];
__device__ int g_fix[E_];

// ---------------------------------------------------------------------------
__global__ void prep_fix_kernel(const float* __restrict__ w,
                                const float* __restrict__ mask) {
    int e = blockIdx.x, t = threadIdx.x;
    #pragma unroll
    for (int i = 0; i < 8; i++) {
        int idx = (e * 256 + t) + i * 8192;
        int m = idx >> 8, d = idx & 255;
        float v = w[idx];
        __half h = __float2half_rn(v);
        __half l = __float2half_rn(v - __half2float(h));
        int hh = m >> 7, mloc = m & 127, c = d >> 6, kk = d & 63;
        int j = hh * 4 + c;
        int off = j * 18432 + mloc * 72 + kk;
        g_w[off] = h;
        g_w[off + 9216] = l;
    }
    if (t == 0) g_fix[e] = 0;
    __syncthreads();

    int warp = t >> 5, lane = t & 31;
    int found = 0;
    for (int r = warp; r < B_ * SEG_; r += 8) {
        int b = r >> 7, l = r & 127;
        const float* row = mask + ((size_t)b * S_ + (size_t)e * SEG_ + l) * S_
                                + (size_t)e * SEG_;
        int allm = 1;
        #pragma unroll
        for (int k = 0; k < 4; k++)
            if (row[lane + 32 * k] != MASKVAL) allm = 0;
        if (__all_sync(0xffffffffu, allm)) { found = 1; break; }
    }
    if (found && lane == 0) atomicOr(&g_fix[e], 1);
}

// ---------------------------------------------------------------------------
__device__ __forceinline__ void ldsm4(unsigned a, unsigned& r0, unsigned& r1,
                                      unsigned& r2, unsigned& r3) {
    asm volatile("ldmatrix.sync.aligned.m8n8.x4.shared.b16 {%0,%1,%2,%3},[%4];"
                 : "=r"(r0), "=r"(r1), "=r"(r2), "=r"(r3) : "r"(a));
}
__device__ __forceinline__ void ldsm4t(unsigned a, unsigned& r0, unsigned& r1,
                                       unsigned& r2, unsigned& r3) {
    asm volatile("ldmatrix.sync.aligned.m8n8.x4.trans.shared.b16 {%0,%1,%2,%3},[%4];"
                 : "=r"(r0), "=r"(r1), "=r"(r2), "=r"(r3) : "r"(a));
}
__device__ __forceinline__ void mma16816(float* c, unsigned a0, unsigned a1,
                                         unsigned a2, unsigned a3,
                                         unsigned b0, unsigned b1) {
    asm("mma.sync.aligned.m16n8k16.row.col.f32.f16.f16.f32 "
        "{%0,%1,%2,%3},{%4,%5,%6,%7},{%8,%9},{%0,%1,%2,%3};"
        : "+f"(c[0]), "+f"(c[1]), "+f"(c[2]), "+f"(c[3])
        : "r"(a0), "r"(a1), "r"(a2), "r"(a3), "r"(b0), "r"(b1));
}
__device__ __forceinline__ unsigned packh2(float a, float b) {
    __half2 p;
    p.x = __float2half_rn(a); p.y = __float2half_rn(b);
    return *(unsigned*)&p;
}
__device__ __forceinline__ void cpasync16(unsigned dst, const void* src) {
    asm volatile("cp.async.cg.shared.global [%0],[%1],16;"
                 :: "r"(dst), "l"(src));
}
#define CP_COMMIT() asm volatile("cp.async.commit_group;" ::: "memory")
#define CP_WAIT0()  asm volatile("cp.async.wait_group 0;" ::: "memory")

// ---------------------------------------------------------------------------
__global__ void __launch_bounds__(256, 1)
main_kernel(const float* __restrict__ hidden,
            const float* __restrict__ maskp,
            const float* __restrict__ bvec,
            float* __restrict__ out)
{
    extern __shared__ char smc[];
    const unsigned sb = (unsigned)__cvta_generic_to_shared(smc);

    float* bias = (float*)(smc + OFF_BIAS);
    float* pool = (float*)(smc + OFF_POOL);

    const int t = threadIdx.x;
    const int lane = t & 31, wi = t >> 5;
    const int rg = lane >> 2, tg = lane & 3;
    const int e = blockIdx.x, bb = blockIdx.y;

    auto load_chunk = [&](int j, int bufi) {
        unsigned dst = sb + OFF_WBUF + (unsigned)bufi * 36864 + (unsigned)t * 16;
        const char* src = (const char*)g_w + (size_t)j * 36864 + (size_t)t * 16;
        #pragma unroll
        for (int i = 0; i < 9; i++)
            cpasync16(dst + i * 4096, src + i * 4096);
        CP_COMMIT();
    };
    load_chunk(0, 0);

    // ---- load seq tile, split fp16 hi/lo ----
    const float* seq_g = hidden + ((size_t)bb * S_ + (size_t)e * SEG_) * D_;
    for (int i = t; i < SEG_ * D_ / 4; i += 256) {
        int l = i >> 6, d = (i & 63) << 2;
        float4 v = *(const float4*)(seq_g + l * D_ + d);
        __half2 h0, h1, l0, l1;
        h0.x = __float2half_rn(v.x); h0.y = __float2half_rn(v.y);
        h1.x = __float2half_rn(v.z); h1.y = __float2half_rn(v.w);
        l0.x = __float2half_rn(v.x - __half2float(h0.x));
        l0.y = __float2half_rn(v.y - __half2float(h0.y));
        l1.x = __float2half_rn(v.z - __half2float(h1.x));
        l1.y = __float2half_rn(v.w - __half2float(h1.y));
        __half* sh = (__half*)(smc + OFF_SEQ_H) + l * SEQ_ST + d;
        __half* sl = (__half*)(smc + OFF_SEQ_L) + l * SEQ_ST + d;
        *(__half2*)sh = h0; *(__half2*)(sh + 2) = h1;
        *(__half2*)sl = l0; *(__half2*)(sl + 2) = l1;
    }
    bias[t] = bvec[t];
    const int fixe = g_fix[e];

    auto adrA = [&](unsigned off, int st, int r0, int k0) -> unsigned {
        int r = r0 + (lane & 7) + ((lane >> 3) & 1) * 8;
        int c = k0 + ((lane >> 4) & 1) * 8;
        return sb + off + (unsigned)((r * st + c) * 2);
    };
    auto adrB = [&](unsigned off, int st, int n0, int k0) -> unsigned {
        int r = n0 + (lane & 7) + ((lane >> 4) & 1) * 8;
        int c = k0 + ((lane >> 3) & 1) * 8;
        return sb + off + (unsigned)((r * st + c) * 2);
    };
    auto adrBt = [&](unsigned off, int st, int k0, int d0) -> unsigned {
        int r = k0 + (lane & 7) + ((lane >> 3) & 1) * 8;
        int c = d0 + ((lane >> 4) & 1) * 8;
        return sb + off + (unsigned)((r * st + c) * 2);
    };

    // ====== Phase A: trsf = tanh(seq_h @ (w_h + w_l)^T + b), streamed =====
    unsigned pAh[64];
    float accA[16][4];

    for (int j = 0; j < 8; j++) {           // chunk: h = j>>2, k64 = j&3
        CP_WAIT0();
        __syncthreads();
        if (j < 7) load_chunk(j + 1, (j + 1) & 1);

        if ((j & 3) == 0) {
            int h = j >> 2;
            #pragma unroll
            for (int jj = 0; jj < 16; jj++) {
                int m0 = h * 128 + jj * 8 + tg * 2;
                float b0 = bias[m0], b1 = bias[m0 + 1];
                accA[jj][0] = b0; accA[jj][1] = b1;
                accA[jj][2] = b0; accA[jj][3] = b1;
            }
        }

        unsigned bufB = OFF_WBUF + (unsigned)(j & 1) * 36864;
        #pragma unroll
        for (int kl = 0; kl < 4; kl++) {
            int kq = (j & 3) * 4 + kl;
            unsigned ah0, ah1, ah2, ah3;
            ldsm4(adrA(OFF_SEQ_H, SEQ_ST, wi * 16, kq * 16), ah0, ah1, ah2, ah3);
            #pragma unroll
            for (int p = 0; p < 8; p++) {
                unsigned bh0, bh1, bh2, bh3, bl0, bl1, bl2, bl3;
                ldsm4(adrB(bufB, WB_ST, p * 16, kl * 16), bh0, bh1, bh2, bh3);
                ldsm4(adrB(bufB + 18432, WB_ST, p * 16, kl * 16), bl0, bl1, bl2, bl3);
                mma16816(accA[2*p],   ah0, ah1, ah2, ah3, bh0, bh1);
                mma16816(accA[2*p+1], ah0, ah1, ah2, ah3, bh2, bh3);
                mma16816(accA[2*p],   ah0, ah1, ah2, ah3, bl0, bl1);
                mma16816(accA[2*p+1], ah0, ah1, ah2, ah3, bl2, bl3);
            }
        }

        if ((j & 3) == 3) {
            int h = j >> 2;
            #pragma unroll
            for (int jj = 0; jj < 16; jj++) {
                float v0 = tanhf(accA[jj][0]), v1 = tanhf(accA[jj][1]);
                float v2 = tanhf(accA[jj][2]), v3 = tanhf(accA[jj][3]);
                int base = h * 32 + (jj >> 1) * 4 + (jj & 1) * 2;
                pAh[base]     = packh2(v0, v1);
                pAh[base + 1] = packh2(v2, v3);
            }
        }
    }

    // ====== Phase B: scores = trsf_h @ (seq_h + seq_l)^T (init = mask) ====
    float accB[16][4];
    {
        int l0 = wi * 16 + rg;
        const float* mr0 = maskp + ((size_t)(bb * S_ + e * SEG_ + l0)) * S_
                                 + (size_t)e * SEG_;
        const float* mr1 = mr0 + (size_t)8 * S_;
        #pragma unroll
        for (int j = 0; j < 16; j++) {
            float2 m0 = *(const float2*)(mr0 + 8 * j + tg * 2);
            float2 m1 = *(const float2*)(mr1 + 8 * j + tg * 2);
            if (fixe && l0 == 0) { m0.x = 0.0f; m0.y = 0.0f; }
            accB[j][0] = m0.x; accB[j][1] = m0.y;
            accB[j][2] = m1.x; accB[j][3] = m1.y;
        }
    }

    #pragma unroll
    for (int kc = 0; kc < 16; kc++) {
        unsigned Ah0 = pAh[kc*4], Ah1 = pAh[kc*4+1],
                 Ah2 = pAh[kc*4+2], Ah3 = pAh[kc*4+3];
        #pragma unroll
        for (int p = 0; p < 8; p++) {
            unsigned bh0, bh1, bh2, bh3, bl0, bl1, bl2, bl3;
            ldsm4(adrB(OFF_SEQ_H, SEQ_ST, p * 16, kc * 16), bh0, bh1, bh2, bh3);
            ldsm4(adrB(OFF_SEQ_L, SEQ_ST, p * 16, kc * 16), bl0, bl1, bl2, bl3);
            mma16816(accB[2*p],   Ah0, Ah1, Ah2, Ah3, bh0, bh1);
            mma16816(accB[2*p+1], Ah0, Ah1, Ah2, Ah3, bh2, bh3);
            mma16816(accB[2*p],   Ah0, Ah1, Ah2, Ah3, bl0, bl1);
            mma16816(accB[2*p+1], Ah0, Ah1, Ah2, Ah3, bl2, bl3);
        }
    }

    // ===== in-register softmax (rows rg and rg+8) =====
    {
        float mx0 = -3.4e38f, mx1 = -3.4e38f;
        #pragma unroll
        for (int j = 0; j < 16; j++) {
            mx0 = fmaxf(mx0, fmaxf(accB[j][0], accB[j][1]));
            mx1 = fmaxf(mx1, fmaxf(accB[j][2], accB[j][3]));
        }
        mx0 = fmaxf(mx0, __shfl_xor_sync(0xffffffffu, mx0, 1));
        mx0 = fmaxf(mx0, __shfl_xor_sync(0xffffffffu, mx0, 2));
        mx1 = fmaxf(mx1, __shfl_xor_sync(0xffffffffu, mx1, 1));
        mx1 = fmaxf(mx1, __shfl_xor_sync(0xffffffffu, mx1, 2));
        float s0 = 0.0f, s1 = 0.0f;
        #pragma unroll
        for (int j = 0; j < 16; j++) {
            accB[j][0] = __expf(accB[j][0] - mx0);
            accB[j][1] = __expf(accB[j][1] - mx0);
            accB[j][2] = __expf(accB[j][2] - mx1);
            accB[j][3] = __expf(accB[j][3] - mx1);
            s0 += accB[j][0] + accB[j][1];
            s1 += accB[j][2] + accB[j][3];
        }
        s0 += __shfl_xor_sync(0xffffffffu, s0, 1);
        s0 += __shfl_xor_sync(0xffffffffu, s0, 2);
        s1 += __shfl_xor_sync(0xffffffffu, s1, 1);
        s1 += __shfl_xor_sync(0xffffffffu, s1, 2);
        float i0 = 1.0f / s0, i1 = 1.0f / s1;
        #pragma unroll
        for (int j = 0; j < 16; j++) {
            accB[j][0] *= i0; accB[j][1] *= i0;
            accB[j][2] *= i1; accB[j][3] *= i1;
        }
    }

    // pack attn to phase-C A-frags (hi only)
    unsigned aCh[32];
    #pragma unroll
    for (int j = 0; j < 16; j++) {
        int base = (j >> 1) * 4 + (j & 1) * 2;
        aCh[base]     = packh2(accB[j][0], accB[j][1]);
        aCh[base + 1] = packh2(accB[j][2], accB[j][3]);
    }

    // ====== Phase C: ctx = attn_h @ (seq_h + seq_l), pooled ===============
    #pragma unroll
    for (int half = 0; half < 2; half++) {
        float accC[16][4];
        #pragma unroll
        for (int j = 0; j < 16; j++)
            #pragma unroll
            for (int q = 0; q < 4; q++) accC[j][q] = 0.0f;

        #pragma unroll
        for (int kc = 0; kc < 8; kc++) {
            unsigned Ah0 = aCh[kc*4], Ah1 = aCh[kc*4+1],
                     Ah2 = aCh[kc*4+2], Ah3 = aCh[kc*4+3];
            #pragma unroll
            for (int p = 0; p < 8; p++) {
                int d0 = half * 128 + p * 16;
                unsigned bh0, bh1, bh2, bh3, bl0, bl1, bl2, bl3;
                ldsm4t(adrBt(OFF_SEQ_H, SEQ_ST, kc * 16, d0), bh0, bh1, bh2, bh3);
                ldsm4t(adrBt(OFF_SEQ_L, SEQ_ST, kc * 16, d0), bl0, bl1, bl2, bl3);
                mma16816(accC[2*p],   Ah0, Ah1, Ah2, Ah3, bh0, bh1);
                mma16816(accC[2*p+1], Ah0, Ah1, Ah2, Ah3, bh2, bh3);
                mma16816(accC[2*p],   Ah0, Ah1, Ah2, Ah3, bl0, bl1);
                mma16816(accC[2*p+1], Ah0, Ah1, Ah2, Ah3, bl2, bl3);
            }
        }
        #pragma unroll
        for (int j = 0; j < 16; j++) {
            float m0 = fmaxf(accC[j][0], accC[j][2]);
            float m1 = fmaxf(accC[j][1], accC[j][3]);
            m0 = fmaxf(m0, __shfl_xor_sync(0xffffffffu, m0, 4));
            m0 = fmaxf(m0, __shfl_xor_sync(0xffffffffu, m0, 8));
            m0 = fmaxf(m0, __shfl_xor_sync(0xffffffffu, m0, 16));
            m1 = fmaxf(m1, __shfl_xor_sync(0xffffffffu, m1, 4));
            m1 = fmaxf(m1, __shfl_xor_sync(0xffffffffu, m1, 8));
            m1 = fmaxf(m1, __shfl_xor_sync(0xffffffffu, m1, 16));
            if (rg == 0) {
                int d = half * 128 + 8 * j + tg * 2;
                pool[wi * 256 + d]     = m0;
                pool[wi * 256 + d + 1] = m1;
            }
        }
    }
    __syncthreads();

    // ---- final pool reduce over 8 warps ----
    {
        float mx = -3.4e38f;
        #pragma unroll
        for (int w = 0; w < 8; w++) mx = fmaxf(mx, pool[w * 256 + t]);
        out[((size_t)bb * E_ + e) * D_ + t] = mx;
    }

    // new_mask[b][e][s] = (s/128 == e)
    float* nm = out + (size_t)B_ * E_ * D_ + ((size_t)bb * E_ + e) * S_;
    for (int s = t; s < S_; s += 256)
        nm[s] = ((s >> 7) == e) ? 1.0f : 0.0f;
}

// ---------------------------------------------------------------------------
extern "C" void kernel_launch(void* const* d_in, const int* in_sizes, int n_in,
                              void* d_out, int out_size) {
    const float* hidden = (const float*)d_in[0];
    const float* mask   = (const float*)d_in[1];
    const float* w      = (const float*)d_in[2];
    const float* bvec   = (const float*)d_in[3];
    float* out = (float*)d_out;
    (void)in_sizes; (void)n_in; (void)out_size;

    prep_fix_kernel<<<E_, 256>>>(w, mask);

    cudaFuncSetAttribute(main_kernel,
                         cudaFuncAttributeMaxDynamicSharedMemorySize, SMEM_TOT);
    main_kernel<<<dim3(E_, B_), 256, SMEM_TOT>>>(hidden, mask, bvec, out);
}

// round 17
// speedup vs baseline: 1.7190x; 1.3956x over previous
#include <cuda_runtime.h>
#include <cuda_fp16.h>
#include <math.h>
#include <stdint.h>

#define B_   8
#define S_   4096
#define D_   256
#define SEG_ 128
#define E_   32
#define MASKVAL (-3.402823466e38f)

#define SEQ_ST 264   // halves
#define WB_ST  72    // halves

// smem byte offsets
#define OFF_SEQ_H 0
#define OFF_SEQ_L 67584
#define OFF_WBUF  135168     // 2 bufs x 36864
#define OFF_BIAS  208896
#define OFF_POOL  209920
#define SMEM_TOT  218112

__device__ __half g_w[8 * 18432];
__device__ int g_fix[E_];        // static zero-init; atomicOr is idempotent per run

// ---------------------------------------------------------------------------
// prep + fix, grid (E_, B_): w-pack sliced across 256 CTAs; per-(e,b) mask scan
// ---------------------------------------------------------------------------
__global__ void prep_fix_kernel(const float* __restrict__ w,
                                const float* __restrict__ mask) {
    int e = blockIdx.x, b = blockIdx.y, t = threadIdx.x;
    {
        int idx = (e * B_ + b) * 256 + t;         // 65536 total, 1 per thread
        int m = idx >> 8, d = idx & 255;
        float v = w[idx];
        __half h = __float2half_rn(v);
        __half l = __float2half_rn(v - __half2float(h));
        int hh = m >> 7, mloc = m & 127, c = d >> 6, kk = d & 63;
        int j = hh * 4 + c;
        int off = j * 18432 + mloc * 72 + kk;
        g_w[off] = h;
        g_w[off + 9216] = l;
    }

    int warp = t >> 5, lane = t & 31;
    int found = 0;
    for (int l = warp; l < SEG_; l += 8) {
        const float* row = mask + ((size_t)b * S_ + (size_t)e * SEG_ + l) * S_
                                + (size_t)e * SEG_;
        int allm = 1;
        #pragma unroll
        for (int k = 0; k < 4; k++)
            if (row[lane + 32 * k] != MASKVAL) allm = 0;
        if (__all_sync(0xffffffffu, allm)) { found = 1; break; }
    }
    if (found && lane == 0) atomicOr(&g_fix[e], 1);
}

// ---------------------------------------------------------------------------
__device__ __forceinline__ void ldsm4(unsigned a, unsigned& r0, unsigned& r1,
                                      unsigned& r2, unsigned& r3) {
    asm volatile("ldmatrix.sync.aligned.m8n8.x4.shared.b16 {%0,%1,%2,%3},[%4];"
                 : "=r"(r0), "=r"(r1), "=r"(r2), "=r"(r3) : "r"(a));
}
__device__ __forceinline__ void ldsm4t(unsigned a, unsigned& r0, unsigned& r1,
                                       unsigned& r2, unsigned& r3) {
    asm volatile("ldmatrix.sync.aligned.m8n8.x4.trans.shared.b16 {%0,%1,%2,%3},[%4];"
                 : "=r"(r0), "=r"(r1), "=r"(r2), "=r"(r3) : "r"(a));
}
__device__ __forceinline__ void mma16816(float* c, unsigned a0, unsigned a1,
                                         unsigned a2, unsigned a3,
                                         unsigned b0, unsigned b1) {
    asm("mma.sync.aligned.m16n8k16.row.col.f32.f16.f16.f32 "
        "{%0,%1,%2,%3},{%4,%5,%6,%7},{%8,%9},{%0,%1,%2,%3};"
        : "+f"(c[0]), "+f"(c[1]), "+f"(c[2]), "+f"(c[3])
        : "r"(a0), "r"(a1), "r"(a2), "r"(a3), "r"(b0), "r"(b1));
}
__device__ __forceinline__ unsigned packh2(float a, float b) {
    __half2 p;
    p.x = __float2half_rn(a); p.y = __float2half_rn(b);
    return *(unsigned*)&p;
}
__device__ __forceinline__ void cpasync16(unsigned dst, const void* src) {
    asm volatile("cp.async.cg.shared.global [%0],[%1],16;"
                 :: "r"(dst), "l"(src));
}
#define CP_COMMIT() asm volatile("cp.async.commit_group;" ::: "memory")
#define CP_WAIT0()  asm volatile("cp.async.wait_group 0;" ::: "memory")

// ---------------------------------------------------------------------------
__global__ void __launch_bounds__(256, 1)
main_kernel(const float* __restrict__ hidden,
            const float* __restrict__ maskp,
            const float* __restrict__ bvec,
            float* __restrict__ out)
{
    extern __shared__ char smc[];
    const unsigned sb = (unsigned)__cvta_generic_to_shared(smc);

    float* bias = (float*)(smc + OFF_BIAS);
    float* pool = (float*)(smc + OFF_POOL);

    const int t = threadIdx.x;
    const int lane = t & 31, wi = t >> 5;
    const int rg = lane >> 2, tg = lane & 3;
    const int e = blockIdx.x, bb = blockIdx.y;

    auto load_chunk = [&](int j, int bufi) {
        unsigned dst = sb + OFF_WBUF + (unsigned)bufi * 36864 + (unsigned)t * 16;
        const char* src = (const char*)g_w + (size_t)j * 36864 + (size_t)t * 16;
        #pragma unroll
        for (int i = 0; i < 9; i++)
            cpasync16(dst + i * 4096, src + i * 4096);
        CP_COMMIT();
    };
    load_chunk(0, 0);

    // ---- load seq tile, split fp16 hi/lo ----
    const float* seq_g = hidden + ((size_t)bb * S_ + (size_t)e * SEG_) * D_;
    for (int i = t; i < SEG_ * D_ / 4; i += 256) {
        int l = i >> 6, d = (i & 63) << 2;
        float4 v = *(const float4*)(seq_g + l * D_ + d);
        __half2 h0, h1, l0, l1;
        h0.x = __float2half_rn(v.x); h0.y = __float2half_rn(v.y);
        h1.x = __float2half_rn(v.z); h1.y = __float2half_rn(v.w);
        l0.x = __float2half_rn(v.x - __half2float(h0.x));
        l0.y = __float2half_rn(v.y - __half2float(h0.y));
        l1.x = __float2half_rn(v.z - __half2float(h1.x));
        l1.y = __float2half_rn(v.w - __half2float(h1.y));
        __half* sh = (__half*)(smc + OFF_SEQ_H) + l * SEQ_ST + d;
        __half* sl = (__half*)(smc + OFF_SEQ_L) + l * SEQ_ST + d;
        *(__half2*)sh = h0; *(__half2*)(sh + 2) = h1;
        *(__half2*)sl = l0; *(__half2*)(sl + 2) = l1;
    }
    bias[t] = bvec[t];
    const int fixe = g_fix[e];

    auto adrA = [&](unsigned off, int st, int r0, int k0) -> unsigned {
        int r = r0 + (lane & 7) + ((lane >> 3) & 1) * 8;
        int c = k0 + ((lane >> 4) & 1) * 8;
        return sb + off + (unsigned)((r * st + c) * 2);
    };
    auto adrB = [&](unsigned off, int st, int n0, int k0) -> unsigned {
        int r = n0 + (lane & 7) + ((lane >> 4) & 1) * 8;
        int c = k0 + ((lane >> 3) & 1) * 8;
        return sb + off + (unsigned)((r * st + c) * 2);
    };
    auto adrBt = [&](unsigned off, int st, int k0, int d0) -> unsigned {
        int r = k0 + (lane & 7) + ((lane >> 3) & 1) * 8;
        int c = d0 + ((lane >> 4) & 1) * 8;
        return sb + off + (unsigned)((r * st + c) * 2);
    };

    // ====== Phase A: trsf = tanh(seq_h @ (w_h + w_l)^T + b), streamed =====
    unsigned pAh[64];
    float accA[16][4];

    for (int j = 0; j < 8; j++) {           // chunk: h = j>>2, k64 = j&3
        CP_WAIT0();
        __syncthreads();
        if (j < 7) load_chunk(j + 1, (j + 1) & 1);

        if ((j & 3) == 0) {
            int h = j >> 2;
            #pragma unroll
            for (int jj = 0; jj < 16; jj++) {
                int m0 = h * 128 + jj * 8 + tg * 2;
                float b0 = bias[m0], b1 = bias[m0 + 1];
                accA[jj][0] = b0; accA[jj][1] = b1;
                accA[jj][2] = b0; accA[jj][3] = b1;
            }
        }

        unsigned bufB = OFF_WBUF + (unsigned)(j & 1) * 36864;
        #pragma unroll
        for (int kl = 0; kl < 4; kl++) {
            int kq = (j & 3) * 4 + kl;
            unsigned ah0, ah1, ah2, ah3;
            ldsm4(adrA(OFF_SEQ_H, SEQ_ST, wi * 16, kq * 16), ah0, ah1, ah2, ah3);
            #pragma unroll
            for (int p = 0; p < 8; p++) {
                unsigned bh0, bh1, bh2, bh3, bl0, bl1, bl2, bl3;
                ldsm4(adrB(bufB, WB_ST, p * 16, kl * 16), bh0, bh1, bh2, bh3);
                ldsm4(adrB(bufB + 18432, WB_ST, p * 16, kl * 16), bl0, bl1, bl2, bl3);
                mma16816(accA[2*p],   ah0, ah1, ah2, ah3, bh0, bh1);
                mma16816(accA[2*p+1], ah0, ah1, ah2, ah3, bh2, bh3);
                mma16816(accA[2*p],   ah0, ah1, ah2, ah3, bl0, bl1);
                mma16816(accA[2*p+1], ah0, ah1, ah2, ah3, bl2, bl3);
            }
        }

        if ((j & 3) == 3) {
            int h = j >> 2;
            #pragma unroll
            for (int jj = 0; jj < 16; jj++) {
                float v0 = tanhf(accA[jj][0]), v1 = tanhf(accA[jj][1]);
                float v2 = tanhf(accA[jj][2]), v3 = tanhf(accA[jj][3]);
                int base = h * 32 + (jj >> 1) * 4 + (jj & 1) * 2;
                pAh[base]     = packh2(v0, v1);
                pAh[base + 1] = packh2(v2, v3);
            }
        }
    }

    // ====== Phase B: scores = trsf_h @ (seq_h + seq_l)^T (init = mask) ====
    float accB[16][4];
    {
        int l0 = wi * 16 + rg;
        const float* mr0 = maskp + ((size_t)(bb * S_ + e * SEG_ + l0)) * S_
                                 + (size_t)e * SEG_;
        const float* mr1 = mr0 + (size_t)8 * S_;
        #pragma unroll
        for (int j = 0; j < 16; j++) {
            float2 m0 = *(const float2*)(mr0 + 8 * j + tg * 2);
            float2 m1 = *(const float2*)(mr1 + 8 * j + tg * 2);
            if (fixe && l0 == 0) { m0.x = 0.0f; m0.y = 0.0f; }
            accB[j][0] = m0.x; accB[j][1] = m0.y;
            accB[j][2] = m1.x; accB[j][3] = m1.y;
        }
    }

    #pragma unroll
    for (int kc = 0; kc < 16; kc++) {
        unsigned Ah0 = pAh[kc*4], Ah1 = pAh[kc*4+1],
                 Ah2 = pAh[kc*4+2], Ah3 = pAh[kc*4+3];
        #pragma unroll
        for (int p = 0; p < 8; p++) {
            unsigned bh0, bh1, bh2, bh3, bl0, bl1, bl2, bl3;
            ldsm4(adrB(OFF_SEQ_H, SEQ_ST, p * 16, kc * 16), bh0, bh1, bh2, bh3);
            ldsm4(adrB(OFF_SEQ_L, SEQ_ST, p * 16, kc * 16), bl0, bl1, bl2, bl3);
            mma16816(accB[2*p],   Ah0, Ah1, Ah2, Ah3, bh0, bh1);
            mma16816(accB[2*p+1], Ah0, Ah1, Ah2, Ah3, bh2, bh3);
            mma16816(accB[2*p],   Ah0, Ah1, Ah2, Ah3, bl0, bl1);
            mma16816(accB[2*p+1], Ah0, Ah1, Ah2, Ah3, bl2, bl3);
        }
    }

    // ===== in-register softmax (rows rg and rg+8) =====
    {
        float mx0 = -3.4e38f, mx1 = -3.4e38f;
        #pragma unroll
        for (int j = 0; j < 16; j++) {
            mx0 = fmaxf(mx0, fmaxf(accB[j][0], accB[j][1]));
            mx1 = fmaxf(mx1, fmaxf(accB[j][2], accB[j][3]));
        }
        mx0 = fmaxf(mx0, __shfl_xor_sync(0xffffffffu, mx0, 1));
        mx0 = fmaxf(mx0, __shfl_xor_sync(0xffffffffu, mx0, 2));
        mx1 = fmaxf(mx1, __shfl_xor_sync(0xffffffffu, mx1, 1));
        mx1 = fmaxf(mx1, __shfl_xor_sync(0xffffffffu, mx1, 2));
        float s0 = 0.0f, s1 = 0.0f;
        #pragma unroll
        for (int j = 0; j < 16; j++) {
            accB[j][0] = __expf(accB[j][0] - mx0);
            accB[j][1] = __expf(accB[j][1] - mx0);
            accB[j][2] = __expf(accB[j][2] - mx1);
            accB[j][3] = __expf(accB[j][3] - mx1);
            s0 += accB[j][0] + accB[j][1];
            s1 += accB[j][2] + accB[j][3];
        }
        s0 += __shfl_xor_sync(0xffffffffu, s0, 1);
        s0 += __shfl_xor_sync(0xffffffffu, s0, 2);
        s1 += __shfl_xor_sync(0xffffffffu, s1, 1);
        s1 += __shfl_xor_sync(0xffffffffu, s1, 2);
        float i0 = 1.0f / s0, i1 = 1.0f / s1;
        #pragma unroll
        for (int j = 0; j < 16; j++) {
            accB[j][0] *= i0; accB[j][1] *= i0;
            accB[j][2] *= i1; accB[j][3] *= i1;
        }
    }

    // pack attn to phase-C A-frags (hi only)
    unsigned aCh[32];
    #pragma unroll
    for (int j = 0; j < 16; j++) {
        int base = (j >> 1) * 4 + (j & 1) * 2;
        aCh[base]     = packh2(accB[j][0], accB[j][1]);
        aCh[base + 1] = packh2(accB[j][2], accB[j][3]);
    }

    // ====== Phase C: ctx = attn_h @ seq_h (single term), pooled ===========
    #pragma unroll
    for (int half = 0; half < 2; half++) {
        float accC[16][4];
        #pragma unroll
        for (int j = 0; j < 16; j++)
            #pragma unroll
            for (int q = 0; q < 4; q++) accC[j][q] = 0.0f;

        #pragma unroll
        for (int kc = 0; kc < 8; kc++) {
            unsigned Ah0 = aCh[kc*4], Ah1 = aCh[kc*4+1],
                     Ah2 = aCh[kc*4+2], Ah3 = aCh[kc*4+3];
            #pragma unroll
            for (int p = 0; p < 8; p++) {
                int d0 = half * 128 + p * 16;
                unsigned bh0, bh1, bh2, bh3;
                ldsm4t(adrBt(OFF_SEQ_H, SEQ_ST, kc * 16, d0), bh0, bh1, bh2, bh3);
                mma16816(accC[2*p],   Ah0, Ah1, Ah2, Ah3, bh0, bh1);
                mma16816(accC[2*p+1], Ah0, Ah1, Ah2, Ah3, bh2, bh3);
            }
        }
        #pragma unroll
        for (int j = 0; j < 16; j++) {
            float m0 = fmaxf(accC[j][0], accC[j][2]);
            float m1 = fmaxf(accC[j][1], accC[j][3]);
            m0 = fmaxf(m0, __shfl_xor_sync(0xffffffffu, m0, 4));
            m0 = fmaxf(m0, __shfl_xor_sync(0xffffffffu, m0, 8));
            m0 = fmaxf(m0, __shfl_xor_sync(0xffffffffu, m0, 16));
            m1 = fmaxf(m1, __shfl_xor_sync(0xffffffffu, m1, 4));
            m1 = fmaxf(m1, __shfl_xor_sync(0xffffffffu, m1, 8));
            m1 = fmaxf(m1, __shfl_xor_sync(0xffffffffu, m1, 16));
            if (rg == 0) {
                int d = half * 128 + 8 * j + tg * 2;
                pool[wi * 256 + d]     = m0;
                pool[wi * 256 + d + 1] = m1;
            }
        }
    }
    __syncthreads();

    // ---- final pool reduce over 8 warps ----
    {
        float mx = -3.4e38f;
        #pragma unroll
        for (int w = 0; w < 8; w++) mx = fmaxf(mx, pool[w * 256 + t]);
        out[((size_t)bb * E_ + e) * D_ + t] = mx;
    }

    // new_mask[b][e][s] = (s/128 == e)
    float* nm = out + (size_t)B_ * E_ * D_ + ((size_t)bb * E_ + e) * S_;
    for (int s = t; s < S_; s += 256)
        nm[s] = ((s >> 7) == e) ? 1.0f : 0.0f;
}

// ---------------------------------------------------------------------------
extern "C" void kernel_launch(void* const* d_in, const int* in_sizes, int n_in,
                              void* d_out, int out_size) {
    const float* hidden = (const float*)d_in[0];
    const float* mask   = (const float*)d_in[1];
    const float* w      = (const float*)d_in[2];
    const float* bvec   = (const float*)d_in[3];
    float* out = (float*)d_out;
    (void)in_sizes; (void)n_in; (void)out_size;

    prep_fix_kernel<<<dim3(E_, B_), 256>>>(w, mask);

    cudaFuncSetAttribute(main_kernel,
                         cudaFuncAttributeMaxDynamicSharedMemorySize, SMEM_TOT);
    main_kernel<<<dim3(E_, B_), 256, SMEM_TOT>>>(hidden, mask, bvec, out);
}